// round 1
// baseline (speedup 1.0000x reference)
#include <cuda_runtime.h>
#include <cstdint>

// ---------------- problem constants ----------------
#define TT       128      // edges per CTA tile
#define THREADS  256
#define PADT     129      // TT + 1 (bank-conflict pad)
#define DD       128      // node feature dim
#define INF      256      // 2*D
#define HID      128
#define LAT      5
#define BETA     10.0f
#define V2C      3.5f

// scalar accumulators (scratch — no allocations allowed)
__device__ double g_rsum;
__device__ double g_klsum;

struct Params {
    const float* x;
    const int*   row;
    const int*   col;
    const float* eps;
    const float *eW0, *eb0, *eW1, *eb1, *eW2, *eb2, *eW3, *eb3;
    const float *dW0, *db0, *dW1, *db1, *dW2, *db2, *dW3, *db3;
    float*       out;
    int          E;
};

__global__ void zero_kernel() { g_rsum = 0.0; g_klsum = 0.0; }

__global__ void fin_kernel(float* out, int E) {
    out[E]     = (float)(g_rsum  / (double)E);
    out[E + 1] = (float)(g_klsum / ((double)E * (double)LAT));
}

// ---------------------------------------------------------------------------
// Micro-GEMM: C[128 x 128] += A_src[K x 128] (col = edge) * W[K x 128-view]
// A_src stored k-major with row stride PADT. W view: W[k*wstride + n], n<128.
// Each thread (16x16 grid) owns an 8x8 C micro-tile. Bs is a 32x128 stage.
// Pattern per slab: load Bs -> sync -> FMA -> sync  (Bs reuse is safe).
// ---------------------------------------------------------------------------
__device__ __forceinline__ void gemm_acc(
    const float* __restrict__ W, int wstride, int K,
    const float* __restrict__ Asrc, float* __restrict__ Bs,
    float c[8][8], int tid)
{
    const int t0 = (tid >> 4) * 8;
    const int n0 = (tid & 15) * 8;

    for (int k0 = 0; k0 < K; k0 += 32) {
        const int KT = min(32, K - k0);
        // stage weight slab (coalesced: n contiguous)
        for (int idx = tid; idx < KT * 128; idx += THREADS) {
            int kk = idx >> 7, n = idx & 127;
            Bs[idx] = W[(size_t)(k0 + kk) * wstride + n];
        }
        __syncthreads();

        #pragma unroll 4
        for (int kk = 0; kk < KT; kk++) {
            float a[8], b[8];
            const float* Ar = Asrc + (size_t)(k0 + kk) * PADT + t0;
            const float* Br = Bs + kk * 128 + n0;
            #pragma unroll
            for (int i = 0; i < 8; i++) a[i] = Ar[i];
            #pragma unroll
            for (int j = 0; j < 8; j++) b[j] = Br[j];
            #pragma unroll
            for (int i = 0; i < 8; i++)
                #pragma unroll
                for (int j = 0; j < 8; j++)
                    c[i][j] = fmaf(a[i], b[j], c[i][j]);
        }
        __syncthreads();
    }
}

__device__ __forceinline__ void init_bias(float c[8][8], const float* __restrict__ b, int tid) {
    const int n0 = (tid & 15) * 8;
    #pragma unroll
    for (int j = 0; j < 8; j++) {
        float bv = b[n0 + j];
        #pragma unroll
        for (int i = 0; i < 8; i++) c[i][j] = bv;
    }
}

template <bool RELU>
__device__ __forceinline__ void writeback(float c[8][8], float* __restrict__ Adst, int tid) {
    const int t0 = (tid >> 4) * 8;
    const int n0 = (tid & 15) * 8;
    #pragma unroll
    for (int i = 0; i < 8; i++)
        #pragma unroll
        for (int j = 0; j < 8; j++) {
            float v = c[i][j];
            if (RELU) v = fmaxf(v, 0.0f);
            Adst[(size_t)(n0 + j) * PADT + t0 + i] = v;
        }
    __syncthreads();
}

// ---------------------------------------------------------------------------
// Fused VAE kernel: one CTA = one tile of 128 edges.
// SMEM: A0 (256 rows) | A1 (128 rows) | Bs (32x128) | idx | rloss | klp
// ---------------------------------------------------------------------------
__global__ void __launch_bounds__(THREADS, 1)
vae_kernel(Params p)
{
    extern __shared__ float smem[];
    float* A0     = smem;                        // 256 * PADT
    float* A1     = smem + 256 * PADT;           // 128 * PADT
    float* Bs     = smem + 384 * PADT;           // 4096
    int*   rows_s = (int*)(Bs + 4096);           // 128
    int*   cols_s = rows_s + TT;                 // 128
    float* rloss  = (float*)(cols_s + TT);       // 128
    float* klp    = rloss + TT;                  // 128

    const int tid   = threadIdx.x;
    const int e0    = blockIdx.x * TT;
    const int valid = min(TT, p.E - e0);

    if (tid < TT) {
        int t = tid;
        int e = e0 + t;
        rows_s[t] = (t < valid) ? p.row[e] : 0;
        cols_s[t] = (t < valid) ? p.col[e] : 0;
        rloss[t]  = 0.0f;
    }
    __syncthreads();

    // ---- gather pair -> A0[k][t], k in [0,256). invalid edges -> 0 ----
    for (int base = 0; base < TT; base += 4) {
        int t = base + (tid >> 6);
        int q = tid & 63;                       // float4 idx within 256 floats
        int node = (q < 32) ? rows_s[t] : cols_s[t];
        int qq = q & 31;
        float4 v = make_float4(0.f, 0.f, 0.f, 0.f);
        if (t < valid)
            v = reinterpret_cast<const float4*>(p.x + (size_t)node * DD)[qq];
        int kb = q * 4;
        A0[(size_t)(kb + 0) * PADT + t] = v.x;
        A0[(size_t)(kb + 1) * PADT + t] = v.y;
        A0[(size_t)(kb + 2) * PADT + t] = v.z;
        A0[(size_t)(kb + 3) * PADT + t] = v.w;
    }
    __syncthreads();

    float c[8][8];

    // ---- encoder ----
    init_bias(c, p.eb0, tid);  gemm_acc(p.eW0, HID, INF, A0, Bs, c, tid);  writeback<true>(c, A1, tid);
    init_bias(c, p.eb1, tid);  gemm_acc(p.eW1, HID, HID, A1, Bs, c, tid);  writeback<true>(c, A0, tid);
    init_bias(c, p.eb2, tid);  gemm_acc(p.eW2, HID, HID, A0, Bs, c, tid);  writeback<true>(c, A1, tid);

    // ---- e3 (128 -> 10) + reparameterize + KL, z -> A0 rows [0,5) ----
    for (int idx = tid; idx < HID * 10; idx += THREADS) Bs[idx] = p.eW3[idx];
    __syncthreads();

    if (tid < TT) {
        int t = tid;
        float s[10];
        #pragma unroll
        for (int l = 0; l < 10; l++) s[l] = p.eb3[l];
        for (int k = 0; k < HID; k++) {
            float a = A1[(size_t)k * PADT + t];
            #pragma unroll
            for (int l = 0; l < 10; l++) s[l] = fmaf(a, Bs[k * 10 + l], s[l]);
        }
        float kls = 0.0f;
        int e = e0 + t;
        #pragma unroll
        for (int l = 0; l < LAT; l++) {
            float mu = s[l], lv = s[LAT + l];
            float z = 0.0f;
            if (t < valid) {
                float ep = p.eps[(size_t)e * LAT + l];
                z = fmaf(ep, expf(0.5f * lv), mu);
                kls += -0.5f * (1.0f + lv - mu * mu - expf(lv));
            }
            A0[(size_t)l * PADT + t] = z;
        }
        klp[t] = kls * BETA;
    }
    __syncthreads();

    // ---- decoder ----
    init_bias(c, p.db0, tid);  gemm_acc(p.dW0, HID, LAT, A0, Bs, c, tid);  writeback<true>(c, A1, tid);
    init_bias(c, p.db1, tid);  gemm_acc(p.dW1, HID, HID, A1, Bs, c, tid);  writeback<true>(c, A0, tid);
    init_bias(c, p.db2, tid);  gemm_acc(p.dW2, HID, HID, A0, Bs, c, tid);  writeback<true>(c, A1, tid);

    // ---- d3 (128 -> 256) in two 128-col halves, fused recon-loss epilogue ----
    const int t0 = (tid >> 4) * 8;
    const int n0 = (tid & 15) * 8;
    for (int h = 0; h < 2; h++) {
        init_bias(c, p.db3 + h * 128, tid);
        gemm_acc(p.dW3 + h * 128, INF, HID, A1, Bs, c, tid);
        const int* nodes = (h == 0) ? rows_s : cols_s;
        #pragma unroll
        for (int i = 0; i < 8; i++) {
            int t = t0 + i;
            if (t < valid) {
                const float* xr = p.x + (size_t)nodes[t] * DD + n0;
                float part = 0.0f;
                #pragma unroll
                for (int j = 0; j < 8; j++) {
                    float d = c[i][j] - xr[j];
                    part = fmaf(d, d, part);
                }
                atomicAdd(&rloss[t], part);
            }
        }
        __syncthreads();
    }

    // ---- affinities + scalar reductions ----
    if (tid < TT) {
        int t = tid;
        float rl = 0.0f;
        if (t < valid) {
            rl = sqrtf(rloss[t]);
            p.out[e0 + t] = 1.0f / fmaf(V2C, rl, 1.0f);
        }
        rloss[t] = rl;
    }
    __syncthreads();

    if (tid == 0) {
        float rs = 0.0f, ks = 0.0f;
        for (int t = 0; t < valid; t++) { rs += rloss[t]; ks += klp[t]; }
        atomicAdd(&g_rsum,  (double)rs);
        atomicAdd(&g_klsum, (double)ks);
    }
}

// ---------------------------------------------------------------------------
extern "C" void kernel_launch(void* const* d_in, const int* in_sizes, int n_in,
                              void* d_out, int out_size)
{
    Params p;
    p.x   = (const float*)d_in[0];
    p.row = (const int*)  d_in[1];
    p.col = (const int*)  d_in[2];
    p.eps = (const float*)d_in[3];
    p.eW0 = (const float*)d_in[4];   p.eb0 = (const float*)d_in[5];
    p.eW1 = (const float*)d_in[6];   p.eb1 = (const float*)d_in[7];
    p.eW2 = (const float*)d_in[8];   p.eb2 = (const float*)d_in[9];
    p.eW3 = (const float*)d_in[10];  p.eb3 = (const float*)d_in[11];
    p.dW0 = (const float*)d_in[12];  p.db0 = (const float*)d_in[13];
    p.dW1 = (const float*)d_in[14];  p.db1 = (const float*)d_in[15];
    p.dW2 = (const float*)d_in[16];  p.db2 = (const float*)d_in[17];
    p.dW3 = (const float*)d_in[18];  p.db3 = (const float*)d_in[19];
    p.out = (float*)d_out;
    p.E   = in_sizes[1];             // edge count (row array)

    const size_t smem_bytes =
        (size_t)(384 * PADT + 4096) * sizeof(float)   // A0+A1 + Bs
        + 2 * TT * sizeof(int)                        // rows, cols
        + 2 * TT * sizeof(float);                     // rloss, klp

    cudaFuncSetAttribute(vae_kernel,
                         cudaFuncAttributeMaxDynamicSharedMemorySize,
                         (int)smem_bytes);

    const int tiles = (p.E + TT - 1) / TT;

    zero_kernel<<<1, 1>>>();
    vae_kernel<<<tiles, THREADS, smem_bytes>>>(p);
    fin_kernel<<<1, 1>>>((float*)d_out, p.E);
}